// round 14
// baseline (speedup 1.0000x reference)
#include <cuda_runtime.h>

#define NN 50000
#define EE 800000

// Scratch (allocation-free: __device__ globals; zero at module load)
__device__ float g_xp[NN * 8];     // x padded to 8 floats/row (32B aligned)
__device__ float g_h1[NN * 64];
__device__ float g_h2[NN * 64];
__device__ float g_agg[NN * 64];   // layer1: stride-8 atomic target; layer2/3: mean store
__device__ float g_t[NN * 32];
__device__ int   g_degi[NN];       // zeroed by k_agg32 at end of each call
__device__ int   g_cur[NN];        // per-node fill counter (zeroed by k_agg32)
__device__ int   g_rp[NN];         // CSR row start, BLOCK-LOCAL (absolute = +g_boff[i>>8])
__device__ int   g_bsum[256];
__device__ int   g_boff[256];
__device__ int   g_csr[EE];        // src node per CSR slot

__device__ __forceinline__ void red_add_v4(float* addr, float4 v) {
    asm volatile("red.global.add.v4.f32 [%0], {%1,%2,%3,%4};"
                 :: "l"(addr), "f"(v.x), "f"(v.y), "f"(v.z), "f"(v.w)
                 : "memory");
}

// ---------------------------------------------------------------------------
__global__ void k_degi(const int* __restrict__ ei) {
    int e = blockIdx.x * blockDim.x + threadIdx.x;
    if (e < EE) atomicAdd(&g_degi[ei[EE + e]], 1);
}

// Block-local exclusive scan of degrees + x padding (fused).
__global__ void k_scanA(const float* __restrict__ x) {
    __shared__ int sm[256];
    int i = blockIdx.x * 256 + threadIdx.x;
    int d = (i < NN) ? g_degi[i] : 0;
    int v = d;
    sm[threadIdx.x] = v; __syncthreads();
#pragma unroll
    for (int o = 1; o < 256; o <<= 1) {
        int t = (threadIdx.x >= o) ? sm[threadIdx.x - o] : 0;
        __syncthreads();
        v += t; sm[threadIdx.x] = v;
        __syncthreads();
    }
    if (i < NN) g_rp[i] = v - d;               // block-local exclusive prefix
    if (threadIdx.x == 255) g_bsum[blockIdx.x] = v;
    // pad this block's 256 nodes of x into g_xp (8 floats per node, tail zero)
    int node0 = blockIdx.x * 256;
    for (int k = threadIdx.x; k < 256 * 8; k += 256) {
        int node = node0 + (k >> 3), c = k & 7;
        if (node < NN)
            g_xp[node * 8 + c] = (c < 5) ? x[node * 5 + c] : 0.f;
    }
}

__global__ void k_scanB(int nblk) {
    __shared__ int sm[256];
    int t = threadIdx.x;
    int d = (t < nblk) ? g_bsum[t] : 0;
    int v = d;
    sm[t] = v; __syncthreads();
#pragma unroll
    for (int o = 1; o < 256; o <<= 1) {
        int u = (t >= o) ? sm[t - o] : 0;
        __syncthreads();
        v += u; sm[t] = v;
        __syncthreads();
    }
    if (t < nblk) g_boff[t] = v - d;
}

// CSR fill + layer-1 feature scatter fused (one pass over edges).
// Absolute slot = block-local rp + block offset + per-node counter.
// x loads come from the 32B-aligned padded copy: 1 sector per edge.
__global__ void k_fillscat(const int* __restrict__ ei) {
    int e = blockIdx.x * blockDim.x + threadIdx.x;
    if (e >= EE) return;
    int s = ei[e], d = ei[EE + e];
    int slot = g_rp[d] + g_boff[d >> 8] + atomicAdd(&g_cur[d], 1);
    g_csr[slot] = s;
    float4 v01 = *(const float4*)&g_xp[s * 8];
    float  v4  = g_xp[s * 8 + 4];
    red_add_v4(&g_agg[d * 8], v01);
    atomicAdd(&g_agg[d * 8 + 4], v4);
}

// Layer 1 combine: h1 = relu(mean5 @ W1l^T + b1 + x @ W1r^T)
__global__ void k_combine1(const float* __restrict__ x,
                           const float* __restrict__ W1l,
                           const float* __restrict__ b1,
                           const float* __restrict__ W1r) {
    int t = blockIdx.x * blockDim.x + threadIdx.x;
    if (t >= NN * 64) return;
    int i = t >> 6, j = t & 63;
    float invd = 1.0f / fmaxf((float)g_degi[i], 1.0f);
    float acc = __ldg(&b1[j]);
#pragma unroll
    for (int c = 0; c < 5; c++) {
        acc = fmaf(g_agg[i * 8 + c] * invd, __ldg(&W1l[j * 5 + c]), acc);
        acc = fmaf(__ldg(&x[i * 5 + c]), __ldg(&W1r[j * 5 + c]), acc);
    }
    g_h1[t] = fmaxf(acc, 0.f);
}

// Layer 2 aggregation: warp per node, CSR gather (proven form, fp32).
__global__ void k_agg64() {
    int w = (blockIdx.x * blockDim.x + threadIdx.x) >> 5;
    if (w >= NN) return;
    int lane = threadIdx.x & 31;
    int beg = g_rp[w] + g_boff[w >> 8], deg = g_degi[w];
    const float2* h1v = (const float2*)g_h1;
    float ax = 0.f, ay = 0.f;
    for (int base = 0; base < deg; base += 32) {
        int n = min(32, deg - base);
        int idx = (base + lane < deg) ? g_csr[beg + base + lane] : 0;
#pragma unroll 8
        for (int k = 0; k < n; k++) {
            int s = __shfl_sync(0xffffffffu, idx, k);
            float2 v = h1v[s * 32 + lane];
            ax += v.x; ay += v.y;
        }
    }
    float invd = 1.0f / fmaxf((float)deg, 1.0f);
    ((float2*)g_agg)[w * 32 + lane] = make_float2(ax * invd, ay * invd);
}

// 64->64 combine + fused layer-3 pre-transform (t = h2 @ W3l^T).
__global__ void k_combine64t3(const float* __restrict__ Wl,
                              const float* __restrict__ b,
                              const float* __restrict__ Wr,
                              const float* __restrict__ W3l) {
    __shared__ float sWl[64 * 64];
    __shared__ float sWr[64 * 64];
    __shared__ float sW3[64 * 32];   // transposed: sW3[c*32 + j]
    __shared__ float sIn[4][64];
    __shared__ float sAg[4][64];
    __shared__ float sH2[4][64];
    int tid = threadIdx.x;
    for (int k = tid; k < 4096; k += 256) {
        int j = k >> 6, c = k & 63;
        sWl[c * 64 + j] = Wl[k];
        sWr[c * 64 + j] = Wr[k];
    }
    for (int k = tid; k < 2048; k += 256) {
        int j = k >> 6, c = k & 63;
        sW3[c * 32 + j] = W3l[k];
    }
    int g = tid >> 6, j = tid & 63;
    float bj = __ldg(&b[j]);
    for (int it = 0; it < 25; it++) {
        int node = (blockIdx.x * 25 + it) * 4 + g;
        __syncthreads();
        sIn[g][j] = g_h1[node * 64 + j];
        sAg[g][j] = g_agg[node * 64 + j];   // already mean-scaled
        __syncthreads();
        float acc = bj;
#pragma unroll
        for (int c = 0; c < 64; c++) {
            acc = fmaf(sAg[g][c], sWl[c * 64 + j], acc);
            acc = fmaf(sIn[g][c], sWr[c * 64 + j], acc);
        }
        float h2 = fmaxf(acc, 0.f);
        g_h2[node * 64 + j] = h2;
        sH2[g][j] = h2;
        __syncthreads();
        // t3 epilogue: 4 nodes x 32 outputs (half the threads)
        if (j < 32) {
            float ta = 0.f;
#pragma unroll
            for (int c = 0; c < 64; c++)
                ta = fmaf(sH2[g][c], sW3[c * 32 + j], ta);
            g_t[node * 32 + j] = ta;
        }
    }
}

// Layer 3 aggregation: warp per node (proven form); restores invariants.
__global__ void k_agg32() {
    int w = (blockIdx.x * blockDim.x + threadIdx.x) >> 5;
    if (w >= NN) return;
    int lane = threadIdx.x & 31;
    int beg = g_rp[w] + g_boff[w >> 8], deg = g_degi[w];
    float acc = 0.f;
    for (int base = 0; base < deg; base += 32) {
        int n = min(32, deg - base);
        int idx = (base + lane < deg) ? g_csr[beg + base + lane] : 0;
#pragma unroll 8
        for (int k = 0; k < n; k++) {
            int s = __shfl_sync(0xffffffffu, idx, k);
            acc += g_t[s * 32 + lane];
        }
    }
    g_agg[w * 32 + lane] = acc * (1.0f / fmaxf((float)deg, 1.0f));
    if (lane == 0) g_degi[w] = 0;   // invariant for next call
    if (lane == 1) g_cur[w] = 0;    // invariant for next call
}

// Final: out = mean32 + b3 + h2 @ W3r^T; re-zeroes g_agg[0..NN*8).
__global__ void k_final(const float* __restrict__ b3,
                        const float* __restrict__ W3r,
                        float* __restrict__ out) {
    __shared__ float sW[64 * 32];
    __shared__ float sIn[8][64];
    int tid = threadIdx.x;
    for (int k = tid; k < 2048; k += 256) {
        int j = k >> 6, c = k & 63;
        sW[c * 32 + j] = W3r[k];
    }
    int g = tid >> 5, j = tid & 31;
    float bj = __ldg(&b3[j]);
    for (int it = 0; it < 10; it++) {
        int node0 = (blockIdx.x * 10 + it) * 8;
        __syncthreads();
        for (int k = tid; k < 512; k += 256) {
            int gg = k >> 6, c = k & 63;
            sIn[gg][c] = g_h2[(node0 + gg) * 64 + c];
        }
        __syncthreads();
        int node = node0 + g;
        float acc = bj + g_agg[node * 32 + j];
#pragma unroll
        for (int c = 0; c < 64; c++)
            acc = fmaf(sIn[g][c], sW[c * 32 + j], acc);
        out[node * 32 + j] = acc;
        if (node < NN / 4) g_agg[node * 32 + j] = 0.f;
    }
}

// ---------------------------------------------------------------------------
extern "C" void kernel_launch(void* const* d_in, const int* in_sizes, int n_in,
                              void* d_out, int out_size) {
    const float* x   = (const float*)d_in[0];
    const int*   ei  = (const int*)d_in[1];
    const float* W1l = (const float*)d_in[2];
    const float* b1  = (const float*)d_in[3];
    const float* W1r = (const float*)d_in[4];
    const float* W2l = (const float*)d_in[5];
    const float* b2  = (const float*)d_in[6];
    const float* W2r = (const float*)d_in[7];
    const float* W3l = (const float*)d_in[8];
    const float* b3  = (const float*)d_in[9];
    const float* W3r = (const float*)d_in[10];
    float* out = (float*)d_out;

    const int T = 256;
    const int SCAN_BLKS = (NN + 255) / 256;   // 196

    k_degi<<<(EE + T - 1) / T, T>>>(ei);
    k_scanA<<<SCAN_BLKS, 256>>>(x);
    k_scanB<<<1, 256>>>(SCAN_BLKS);
    k_fillscat<<<(EE + T - 1) / T, T>>>(ei);  // 4th launch -> ncu capture

    // layer 1
    k_combine1<<<(NN * 64 + T - 1) / T, T>>>(x, W1l, b1, W1r);

    // layer 2 (+ fused layer-3 pre-transform)
    k_agg64<<<(NN * 32 + T - 1) / T, T>>>();
    k_combine64t3<<<NN / 100, T>>>(W2l, b2, W2r, W3l);   // 500 blocks

    // layer 3 aggregation + final combine
    k_agg32<<<(NN * 32 + T - 1) / T, T>>>();
    k_final<<<NN / 80, T>>>(b3, W3r, out);               // 625 blocks
}

// round 15
// speedup vs baseline: 1.4494x; 1.4494x over previous
#include <cuda_runtime.h>

#define NN 50000
#define EE 800000

// Scratch (allocation-free: __device__ globals; zero at module load)
__device__ float g_xp[NN * 8];     // x padded to 8 floats/row (32B-aligned rows)
__device__ float g_h1[NN * 64];
__device__ float g_h2[NN * 64];
__device__ float g_agg[NN * 64];   // layer1: stride-8 atomic target; layer2/3: mean store
__device__ float g_t[NN * 32];
__device__ int   g_degi[NN];
__device__ int   g_cur[NN];        // running CSR cursor (scanC sets = rp)
__device__ int   g_rp[NN];         // CSR row start (exclusive prefix of deg)
__device__ int   g_bsum[256];
__device__ int   g_boff[256];
__device__ int   g_csr[EE];        // src node per CSR slot

__device__ __forceinline__ void red_add_v4(float* addr, float4 v) {
    asm volatile("red.global.add.v4.f32 [%0], {%1,%2,%3,%4};"
                 :: "l"(addr), "f"(v.x), "f"(v.y), "f"(v.z), "f"(v.w)
                 : "memory");
}

// ---------------------------------------------------------------------------
__global__ void k_init() {
    int i = blockIdx.x * blockDim.x + threadIdx.x;
    if (i < NN * 8) g_agg[i] = 0.f;
    if (i < NN) g_degi[i] = 0;
}

__global__ void k_degi(const int* __restrict__ ei) {
    int e = blockIdx.x * blockDim.x + threadIdx.x;
    if (e < EE) atomicAdd(&g_degi[ei[EE + e]], 1);
}

// Exclusive scan of degrees (coalesced) + pad x into g_xp (fused, coalesced).
__global__ void k_scanA(const float* __restrict__ x) {
    __shared__ int sm[256];
    int i = blockIdx.x * 256 + threadIdx.x;
    int d = (i < NN) ? g_degi[i] : 0;
    int v = d;
    sm[threadIdx.x] = v; __syncthreads();
#pragma unroll
    for (int o = 1; o < 256; o <<= 1) {
        int t = (threadIdx.x >= o) ? sm[threadIdx.x - o] : 0;
        __syncthreads();
        v += t; sm[threadIdx.x] = v;
        __syncthreads();
    }
    if (i < NN) g_rp[i] = v - d;
    if (threadIdx.x == 255) g_bsum[blockIdx.x] = v;
    // pad this block's 256 nodes of x (8 floats/node, tail zero); coalesced
    int node0 = blockIdx.x * 256;
    for (int k = threadIdx.x; k < 256 * 8; k += 256) {
        int node = node0 + (k >> 3), c = k & 7;
        if (node < NN)
            g_xp[node * 8 + c] = (c < 5) ? x[node * 5 + c] : 0.f;
    }
}

__global__ void k_scanB(int nblk) {
    __shared__ int sm[256];
    int t = threadIdx.x;
    int d = (t < nblk) ? g_bsum[t] : 0;
    int v = d;
    sm[t] = v; __syncthreads();
#pragma unroll
    for (int o = 1; o < 256; o <<= 1) {
        int u = (t >= o) ? sm[t - o] : 0;
        __syncthreads();
        v += u; sm[t] = v;
        __syncthreads();
    }
    if (t < nblk) g_boff[t] = v - d;
}
__global__ void k_scanC() {
    int i = blockIdx.x * 256 + threadIdx.x;
    if (i < NN) {
        int r = g_rp[i] + g_boff[i >> 8];
        g_rp[i] = r;
        g_cur[i] = r;     // absolute cursor for fillscat (single atomic per edge)
    }
}

// CSR fill + layer-1 feature scatter fused (one pass over edges).
// Slot: ONE atomicAdd on the absolute cursor (proven fast form).
// Features: one LDG.128 + one LDG.32 from the padded row (single 32B sector).
__global__ void k_fillscat(const int* __restrict__ ei) {
    int e = blockIdx.x * blockDim.x + threadIdx.x;
    if (e >= EE) return;
    int s = ei[e], d = ei[EE + e];
    int slot = atomicAdd(&g_cur[d], 1);
    g_csr[slot] = s;
    float4 v01 = *(const float4*)&g_xp[s * 8];
    float  v4  = g_xp[s * 8 + 4];
    red_add_v4(&g_agg[d * 8], v01);
    atomicAdd(&g_agg[d * 8 + 4], v4);
}

// Layer 1 combine: h1 = relu(mean5 @ W1l^T + b1 + x @ W1r^T)
__global__ void k_combine1(const float* __restrict__ x,
                           const float* __restrict__ W1l,
                           const float* __restrict__ b1,
                           const float* __restrict__ W1r) {
    int t = blockIdx.x * blockDim.x + threadIdx.x;
    if (t >= NN * 64) return;
    int i = t >> 6, j = t & 63;
    float invd = 1.0f / fmaxf((float)g_degi[i], 1.0f);
    float acc = __ldg(&b1[j]);
#pragma unroll
    for (int c = 0; c < 5; c++) {
        acc = fmaf(g_agg[i * 8 + c] * invd, __ldg(&W1l[j * 5 + c]), acc);
        acc = fmaf(__ldg(&x[i * 5 + c]), __ldg(&W1r[j * 5 + c]), acc);
    }
    g_h1[t] = fmaxf(acc, 0.f);
}

// Layer 2 aggregation: warp per node, CSR gather (proven form, fp32).
__global__ void k_agg64() {
    int w = (blockIdx.x * blockDim.x + threadIdx.x) >> 5;
    if (w >= NN) return;
    int lane = threadIdx.x & 31;
    int beg = g_rp[w], deg = g_degi[w];
    const float2* h1v = (const float2*)g_h1;
    float ax = 0.f, ay = 0.f;
    for (int base = 0; base < deg; base += 32) {
        int n = min(32, deg - base);
        int idx = (base + lane < deg) ? g_csr[beg + base + lane] : 0;
#pragma unroll 8
        for (int k = 0; k < n; k++) {
            int s = __shfl_sync(0xffffffffu, idx, k);
            float2 v = h1v[s * 32 + lane];
            ax += v.x; ay += v.y;
        }
    }
    float invd = 1.0f / fmaxf((float)deg, 1.0f);
    ((float2*)g_agg)[w * 32 + lane] = make_float2(ax * invd, ay * invd);
}

// 64->64 combine; 100 nodes per block (proven geometry, no t3 fusion).
__global__ void k_combine64(const float* __restrict__ Wl,
                            const float* __restrict__ b,
                            const float* __restrict__ Wr) {
    __shared__ float sWl[64 * 64];
    __shared__ float sWr[64 * 64];
    __shared__ float sIn[4][64];
    __shared__ float sAg[4][64];
    int tid = threadIdx.x;
    for (int k = tid; k < 4096; k += 256) {
        int j = k >> 6, c = k & 63;
        sWl[c * 64 + j] = Wl[k];
        sWr[c * 64 + j] = Wr[k];
    }
    int g = tid >> 6, j = tid & 63;
    float bj = __ldg(&b[j]);
    for (int it = 0; it < 25; it++) {
        int node = (blockIdx.x * 25 + it) * 4 + g;
        __syncthreads();
        sIn[g][j] = g_h1[node * 64 + j];
        sAg[g][j] = g_agg[node * 64 + j];   // already mean-scaled
        __syncthreads();
        float acc = bj;
#pragma unroll
        for (int c = 0; c < 64; c++) {
            acc = fmaf(sAg[g][c], sWl[c * 64 + j], acc);
            acc = fmaf(sIn[g][c], sWr[c * 64 + j], acc);
        }
        g_h2[node * 64 + j] = fmaxf(acc, 0.f);
    }
}

// Layer 3 pre-transform: t = h2 @ W3l^T. 80 nodes per block (proven geometry).
__global__ void k_t3(const float* __restrict__ W3l) {
    __shared__ float sW[64 * 32];
    __shared__ float sIn[8][64];
    int tid = threadIdx.x;
    for (int k = tid; k < 2048; k += 256) {
        int j = k >> 6, c = k & 63;
        sW[c * 32 + j] = W3l[k];
    }
    int g = tid >> 5, j = tid & 31;
    for (int it = 0; it < 10; it++) {
        int node0 = (blockIdx.x * 10 + it) * 8;
        __syncthreads();
        for (int k = tid; k < 512; k += 256) {
            int gg = k >> 6, c = k & 63;
            sIn[gg][c] = g_h2[(node0 + gg) * 64 + c];
        }
        __syncthreads();
        float acc = 0.f;
#pragma unroll
        for (int c = 0; c < 64; c++)
            acc = fmaf(sIn[g][c], sW[c * 32 + j], acc);
        g_t[(node0 + g) * 32 + j] = acc;
    }
}

// Layer 3 aggregation: warp per node (proven form).
__global__ void k_agg32() {
    int w = (blockIdx.x * blockDim.x + threadIdx.x) >> 5;
    if (w >= NN) return;
    int lane = threadIdx.x & 31;
    int beg = g_rp[w], deg = g_degi[w];
    float acc = 0.f;
    for (int base = 0; base < deg; base += 32) {
        int n = min(32, deg - base);
        int idx = (base + lane < deg) ? g_csr[beg + base + lane] : 0;
#pragma unroll 8
        for (int k = 0; k < n; k++) {
            int s = __shfl_sync(0xffffffffu, idx, k);
            acc += g_t[s * 32 + lane];
        }
    }
    g_agg[w * 32 + lane] = acc * (1.0f / fmaxf((float)deg, 1.0f));
}

// Final: out = mean32 + b3 + h2 @ W3r^T. 80 nodes per block (proven geometry).
__global__ void k_final(const float* __restrict__ b3,
                        const float* __restrict__ W3r,
                        float* __restrict__ out) {
    __shared__ float sW[64 * 32];
    __shared__ float sIn[8][64];
    int tid = threadIdx.x;
    for (int k = tid; k < 2048; k += 256) {
        int j = k >> 6, c = k & 63;
        sW[c * 32 + j] = W3r[k];
    }
    int g = tid >> 5, j = tid & 31;
    float bj = __ldg(&b3[j]);
    for (int it = 0; it < 10; it++) {
        int node0 = (blockIdx.x * 10 + it) * 8;
        __syncthreads();
        for (int k = tid; k < 512; k += 256) {
            int gg = k >> 6, c = k & 63;
            sIn[gg][c] = g_h2[(node0 + gg) * 64 + c];
        }
        __syncthreads();
        int node = node0 + g;
        float acc = bj + g_agg[node * 32 + j];
#pragma unroll
        for (int c = 0; c < 64; c++)
            acc = fmaf(sIn[g][c], sW[c * 32 + j], acc);
        out[node * 32 + j] = acc;
    }
}

// ---------------------------------------------------------------------------
extern "C" void kernel_launch(void* const* d_in, const int* in_sizes, int n_in,
                              void* d_out, int out_size) {
    const float* x   = (const float*)d_in[0];
    const int*   ei  = (const int*)d_in[1];
    const float* W1l = (const float*)d_in[2];
    const float* b1  = (const float*)d_in[3];
    const float* W1r = (const float*)d_in[4];
    const float* W2l = (const float*)d_in[5];
    const float* b2  = (const float*)d_in[6];
    const float* W2r = (const float*)d_in[7];
    const float* W3l = (const float*)d_in[8];
    const float* b3  = (const float*)d_in[9];
    const float* W3r = (const float*)d_in[10];
    float* out = (float*)d_out;

    const int T = 256;
    const int SCAN_BLKS = (NN + 255) / 256;   // 196

    k_init<<<(NN * 8 + T - 1) / T, T>>>();
    k_degi<<<(EE + T - 1) / T, T>>>(ei);
    k_scanA<<<SCAN_BLKS, 256>>>(x);
    k_scanB<<<1, 256>>>(SCAN_BLKS);
    k_scanC<<<SCAN_BLKS, 256>>>();
    k_fillscat<<<(EE + T - 1) / T, T>>>(ei);

    // layer 1
    k_combine1<<<(NN * 64 + T - 1) / T, T>>>(x, W1l, b1, W1r);

    // layer 2
    k_agg64<<<(NN * 32 + T - 1) / T, T>>>();
    k_combine64<<<NN / 100, T>>>(W2l, b2, W2r);  // 500 blocks

    // layer 3
    k_t3<<<NN / 80, T>>>(W3l);                   // 625 blocks
    k_agg32<<<(NN * 32 + T - 1) / T, T>>>();
    k_final<<<NN / 80, T>>>(b3, W3r, out);       // 625 blocks
}

// round 17
// speedup vs baseline: 1.5825x; 1.0918x over previous
#include <cuda_runtime.h>

#define NN 50000
#define EE 800000

typedef unsigned long long ull;

// Scratch (allocation-free: __device__ globals; zero at module load)
__device__ float g_h1[NN * 64];
__device__ float g_h2[NN * 64];
__device__ float g_agg[NN * 64];   // layer1: stride-8 atomic target; layer2/3: mean store
__device__ float g_t[NN * 32];
__device__ int   g_degi[NN];
__device__ int   g_cur[NN];        // running CSR cursor (scanC sets = rp)
__device__ int   g_rp[NN];         // CSR row start (exclusive prefix of deg)
__device__ int   g_bsum[256];
__device__ int   g_boff[256];
__device__ int   g_csr[EE];        // src node per CSR slot

__device__ __forceinline__ void red_add_v4(float* addr, float4 v) {
    asm volatile("red.global.add.v4.f32 [%0], {%1,%2,%3,%4};"
                 :: "l"(addr), "f"(v.x), "f"(v.y), "f"(v.z), "f"(v.w)
                 : "memory");
}
#define ADD_F32X2(out, a, b) \
    asm("add.rn.f32x2 %0, %1, %2;" : "=l"(out) : "l"(a), "l"(b))
#define FMA_F32X2(d, a, b, c) \
    asm("fma.rn.f32x2 %0, %1, %2, %3;" : "=l"(d) : "l"(a), "l"(b), "l"(c))

// ---------------------------------------------------------------------------
__global__ void k_init() {
    int i = blockIdx.x * blockDim.x + threadIdx.x;
    if (i < NN * 8) g_agg[i] = 0.f;
    if (i < NN) g_degi[i] = 0;
}

__global__ void k_degi(const int* __restrict__ ei) {
    int e = blockIdx.x * blockDim.x + threadIdx.x;
    if (e < EE) atomicAdd(&g_degi[ei[EE + e]], 1);
}

// Exclusive scan of degrees (coalesced, 3 kernels).
__global__ void k_scanA() {
    __shared__ int sm[256];
    int i = blockIdx.x * 256 + threadIdx.x;
    int d = (i < NN) ? g_degi[i] : 0;
    int v = d;
    sm[threadIdx.x] = v; __syncthreads();
#pragma unroll
    for (int o = 1; o < 256; o <<= 1) {
        int t = (threadIdx.x >= o) ? sm[threadIdx.x - o] : 0;
        __syncthreads();
        v += t; sm[threadIdx.x] = v;
        __syncthreads();
    }
    if (i < NN) g_rp[i] = v - d;
    if (threadIdx.x == 255) g_bsum[blockIdx.x] = v;
}
__global__ void k_scanB(int nblk) {
    __shared__ int sm[256];
    int t = threadIdx.x;
    int d = (t < nblk) ? g_bsum[t] : 0;
    int v = d;
    sm[t] = v; __syncthreads();
#pragma unroll
    for (int o = 1; o < 256; o <<= 1) {
        int u = (t >= o) ? sm[t - o] : 0;
        __syncthreads();
        v += u; sm[t] = v;
        __syncthreads();
    }
    if (t < nblk) g_boff[t] = v - d;
}
__global__ void k_scanC() {
    int i = blockIdx.x * 256 + threadIdx.x;
    if (i < NN) {
        int r = g_rp[i] + g_boff[i >> 8];
        g_rp[i] = r;
        g_cur[i] = r;     // absolute cursor for fillscat (single atomic per edge)
    }
}

// CSR fill + layer-1 feature scatter fused (one pass over edges).
__global__ void k_fillscat(const int* __restrict__ ei,
                           const float* __restrict__ x) {
    int e = blockIdx.x * blockDim.x + threadIdx.x;
    if (e >= EE) return;
    int s = ei[e], d = ei[EE + e];
    int slot = atomicAdd(&g_cur[d], 1);
    g_csr[slot] = s;
    const float* xr = x + s * 5;
    float4 v = make_float4(__ldg(xr), __ldg(xr + 1), __ldg(xr + 2), __ldg(xr + 3));
    red_add_v4(&g_agg[d * 8], v);
    atomicAdd(&g_agg[d * 8 + 4], __ldg(xr + 4));
}

// Layer 1 combine: h1 = relu(mean5 @ W1l^T + b1 + x @ W1r^T)
__global__ void k_combine1(const float* __restrict__ x,
                           const float* __restrict__ W1l,
                           const float* __restrict__ b1,
                           const float* __restrict__ W1r) {
    int t = blockIdx.x * blockDim.x + threadIdx.x;
    if (t >= NN * 64) return;
    int i = t >> 6, j = t & 63;
    float invd = 1.0f / fmaxf((float)g_degi[i], 1.0f);
    float acc = __ldg(&b1[j]);
#pragma unroll
    for (int c = 0; c < 5; c++) {
        acc = fmaf(g_agg[i * 8 + c] * invd, __ldg(&W1l[j * 5 + c]), acc);
        acc = fmaf(__ldg(&x[i * 5 + c]), __ldg(&W1r[j * 5 + c]), acc);
    }
    g_h1[t] = fmaxf(acc, 0.f);
}

// Layer 2 aggregation: warp per node (proven geometry), packed f32x2 accumulate.
__global__ void k_agg64() {
    int w = (blockIdx.x * blockDim.x + threadIdx.x) >> 5;
    if (w >= NN) return;
    int lane = threadIdx.x & 31;
    int beg = g_rp[w], deg = g_degi[w];
    const ull* h1v = (const ull*)g_h1;   // 32 x 8B per node row
    ull acc2 = 0ull;                     // packed {0.f, 0.f}
    for (int base = 0; base < deg; base += 32) {
        int n = min(32, deg - base);
        int idx = (base + lane < deg) ? g_csr[beg + base + lane] : 0;
#pragma unroll 8
        for (int k = 0; k < n; k++) {
            int s = __shfl_sync(0xffffffffu, idx, k);
            ull v = h1v[s * 32 + lane];
            ADD_F32X2(acc2, acc2, v);
        }
    }
    float2 a = *(float2*)&acc2;
    float invd = 1.0f / fmaxf((float)deg, 1.0f);
    ((float2*)g_agg)[w * 32 + lane] = make_float2(a.x * invd, a.y * invd);
}

// 64->64 combine; 100 nodes per block; packed FFMA2 over {Wl,Wr}x{agg,h1}.
__global__ void k_combine64(const float* __restrict__ Wl,
                            const float* __restrict__ b,
                            const float* __restrict__ Wr) {
    __shared__ float2 sW2[64 * 64];   // 32KB: [c*64+j] = {Wl[j,c], Wr[j,c]}
    __shared__ float2 sA2[4][64];     // [g][c] = {agg[c], h1[c]}
    int tid = threadIdx.x;
    for (int k = tid; k < 4096; k += 256) {
        int j = k >> 6, c = k & 63;
        sW2[c * 64 + j] = make_float2(Wl[k], Wr[k]);
    }
    int g = tid >> 6, j = tid & 63;
    float bj = __ldg(&b[j]);
    for (int it = 0; it < 25; it++) {
        int node = (blockIdx.x * 25 + it) * 4 + g;
        __syncthreads();
        sA2[g][j] = make_float2(g_agg[node * 64 + j], g_h1[node * 64 + j]);
        __syncthreads();
        ull acc2 = 0ull;
#pragma unroll
        for (int c = 0; c < 64; c++) {
            ull a = *(const ull*)&sA2[g][c];
            ull wv = *(const ull*)&sW2[c * 64 + j];
            FMA_F32X2(acc2, a, wv, acc2);
        }
        float2 r = *(float2*)&acc2;
        g_h2[node * 64 + j] = fmaxf(r.x + r.y + bj, 0.f);
    }
}

// Layer 3 pre-transform: t = h2 @ W3l^T. 80 nodes/block; packed channel pairs.
__global__ void k_t3(const float* __restrict__ W3l) {
    __shared__ float2 sWp[32 * 32];   // [c2*32+j] = {W[j,2c2], W[j,2c2+1]}
    __shared__ float sIn[8][64];
    int tid = threadIdx.x;
    for (int k = tid; k < 1024; k += 256) {
        int c2 = k >> 5, j = k & 31;
        sWp[k] = make_float2(W3l[j * 64 + 2 * c2], W3l[j * 64 + 2 * c2 + 1]);
    }
    int g = tid >> 5, j = tid & 31;
    for (int it = 0; it < 10; it++) {
        int node0 = (blockIdx.x * 10 + it) * 8;
        __syncthreads();
        for (int k = tid; k < 512; k += 256) {
            int gg = k >> 6, c = k & 63;
            sIn[gg][c] = g_h2[(node0 + gg) * 64 + c];
        }
        __syncthreads();
        const ull* ip = (const ull*)sIn[g];
        ull acc2 = 0ull;
#pragma unroll
        for (int c2 = 0; c2 < 32; c2++) {
            ull a = ip[c2];
            ull wv = *(const ull*)&sWp[c2 * 32 + j];
            FMA_F32X2(acc2, a, wv, acc2);
        }
        float2 r = *(float2*)&acc2;
        g_t[(node0 + g) * 32 + j] = r.x + r.y;
    }
}

// Layer 3 aggregation: warp per node (proven form, unchanged).
__global__ void k_agg32() {
    int w = (blockIdx.x * blockDim.x + threadIdx.x) >> 5;
    if (w >= NN) return;
    int lane = threadIdx.x & 31;
    int beg = g_rp[w], deg = g_degi[w];
    float acc = 0.f;
    for (int base = 0; base < deg; base += 32) {
        int n = min(32, deg - base);
        int idx = (base + lane < deg) ? g_csr[beg + base + lane] : 0;
#pragma unroll 8
        for (int k = 0; k < n; k++) {
            int s = __shfl_sync(0xffffffffu, idx, k);
            acc += g_t[s * 32 + lane];
        }
    }
    g_agg[w * 32 + lane] = acc * (1.0f / fmaxf((float)deg, 1.0f));
}

// Final: out = mean32 + b3 + h2 @ W3r^T. 80 nodes/block; packed channel pairs.
__global__ void k_final(const float* __restrict__ b3,
                        const float* __restrict__ W3r,
                        float* __restrict__ out) {
    __shared__ float2 sWp[32 * 32];   // [c2*32+j] = {W[j,2c2], W[j,2c2+1]}
    __shared__ float sIn[8][64];
    int tid = threadIdx.x;
    for (int k = tid; k < 1024; k += 256) {
        int c2 = k >> 5, j = k & 31;
        sWp[k] = make_float2(W3r[j * 64 + 2 * c2], W3r[j * 64 + 2 * c2 + 1]);
    }
    int g = tid >> 5, j = tid & 31;
    float bj = __ldg(&b3[j]);
    for (int it = 0; it < 10; it++) {
        int node0 = (blockIdx.x * 10 + it) * 8;
        __syncthreads();
        for (int k = tid; k < 512; k += 256) {
            int gg = k >> 6, c = k & 63;
            sIn[gg][c] = g_h2[(node0 + gg) * 64 + c];
        }
        __syncthreads();
        int node = node0 + g;
        const ull* ip = (const ull*)sIn[g];
        ull acc2 = 0ull;
#pragma unroll
        for (int c2 = 0; c2 < 32; c2++) {
            ull a = ip[c2];
            ull wv = *(const ull*)&sWp[c2 * 32 + j];
            FMA_F32X2(acc2, a, wv, acc2);
        }
        float2 r = *(float2*)&acc2;
        out[node * 32 + j] = bj + g_agg[node * 32 + j] + r.x + r.y;
    }
}

// ---------------------------------------------------------------------------
extern "C" void kernel_launch(void* const* d_in, const int* in_sizes, int n_in,
                              void* d_out, int out_size) {
    const float* x   = (const float*)d_in[0];
    const int*   ei  = (const int*)d_in[1];
    const float* W1l = (const float*)d_in[2];
    const float* b1  = (const float*)d_in[3];
    const float* W1r = (const float*)d_in[4];
    const float* W2l = (const float*)d_in[5];
    const float* b2  = (const float*)d_in[6];
    const float* W2r = (const float*)d_in[7];
    const float* W3l = (const float*)d_in[8];
    const float* b3  = (const float*)d_in[9];
    const float* W3r = (const float*)d_in[10];
    float* out = (float*)d_out;

    const int T = 256;
    const int SCAN_BLKS = (NN + 255) / 256;   // 196

    k_init<<<(NN * 8 + T - 1) / T, T>>>();
    k_degi<<<(EE + T - 1) / T, T>>>(ei);
    k_scanA<<<SCAN_BLKS, 256>>>();
    k_scanB<<<1, 256>>>(SCAN_BLKS);
    k_scanC<<<SCAN_BLKS, 256>>>();
    k_fillscat<<<(EE + T - 1) / T, T>>>(ei, x);

    // layer 1
    k_combine1<<<(NN * 64 + T - 1) / T, T>>>(x, W1l, b1, W1r);

    // layer 2
    k_agg64<<<(NN * 32 + T - 1) / T, T>>>();
    k_combine64<<<NN / 100, T>>>(W2l, b2, W2r);  // 500 blocks

    // layer 3
    k_t3<<<NN / 80, T>>>(W3l);                   // 625 blocks
    k_agg32<<<(NN * 32 + T - 1) / T, T>>>();
    k_final<<<NN / 80, T>>>(b3, W3r, out);       // 625 blocks
}